// round 3
// baseline (speedup 1.0000x reference)
#include <cuda_runtime.h>
#include <math.h>

#define VOCAB 30000
#define HID   512
#define NCLS  4
#define NEDGE 4096
#define NNODE (NEDGE + 1)
#define KW    32
#define G3    (3 * HID)      // 1536
#define NLEV_MAX 64          // >> expected tree depth (~23 for random recursive tree)

// -------------------- static device scratch (no allocations allowed) --------
__device__ float d_Et[(size_t)VOCAB * HID];     // transposed embedding table
__device__ float d_X [(size_t)NEDGE * HID];     // per-node input x
__device__ float d_GI[(size_t)NEDGE * G3];      // W_ih @ x + b_ih, node-major
__device__ float d_GH[(size_t)NEDGE * G3];      // W_hh @ h_parent + b_hh
__device__ float d_H [(size_t)NNODE * HID];     // hidden states
__device__ int   d_order[NEDGE];
__device__ int   d_levelStart[NLEV_MAX + 2];

// -------------------- 1) transpose E (HID,VOCAB) -> (VOCAB,HID) -------------
__global__ void k_transpose(const float* __restrict__ E) {
    __shared__ float t[32][33];
    int v0 = blockIdx.x * 32, h0 = blockIdx.y * 32;
    int vx = v0 + threadIdx.x;
#pragma unroll
    for (int i = 0; i < 32; i += 8) {
        int h = h0 + threadIdx.y + i;
        if (vx < VOCAB) t[threadIdx.y + i][threadIdx.x] = E[(size_t)h * VOCAB + vx];
    }
    __syncthreads();
    int hx = h0 + threadIdx.x;
#pragma unroll
    for (int i = 0; i < 32; i += 8) {
        int v = v0 + threadIdx.y + i;
        if (v < VOCAB) d_Et[(size_t)v * HID + hx] = t[threadIdx.x][threadIdx.y + i];
    }
}

// -------------------- 2) x[c] = sum_k Et[idx[c][k]] * w[c][k] ---------------
__global__ void k_embed(const float* __restrict__ word, const int* __restrict__ widx) {
    int c = blockIdx.x;
    __shared__ int   si[KW];
    __shared__ float sw[KW];
    if (threadIdx.x < KW) {
        si[threadIdx.x] = widx[c * KW + threadIdx.x];
        sw[threadIdx.x] = word[c * KW + threadIdx.x];
    }
    __syncthreads();
    int h = threadIdx.x;                 // 128 threads, each handles 4 h values
    float a0 = 0.f, a1 = 0.f, a2 = 0.f, a3 = 0.f;
#pragma unroll 4
    for (int k = 0; k < KW; k++) {
        const float* ep = &d_Et[(size_t)si[k] * HID];
        float wk = sw[k];
        a0 += ep[h]       * wk;
        a1 += ep[h + 128] * wk;
        a2 += ep[h + 256] * wk;
        a3 += ep[h + 384] * wk;
    }
    float* xp = &d_X[(size_t)c * HID];
    xp[h] = a0; xp[h + 128] = a1; xp[h + 256] = a2; xp[h + 384] = a3;
}

// -------------------- 3) GI = X @ W_ih^T + b_ih  (4096 x 1536, K=512) -------
#define BM 128
#define BN 128
#define BK 8
__global__ __launch_bounds__(256) void k_gi(const float* __restrict__ Wih,
                                            const float* __restrict__ bih) {
    __shared__ float As[BK][BM];
    __shared__ float Bs[BK][BN];
    int m0 = blockIdx.y * BM, n0 = blockIdx.x * BN;
    int tid = threadIdx.x;
    int lm = tid >> 1, lk = (tid & 1) * 4;     // load map: 2 threads per row
    int ty = tid >> 4, tx = tid & 15;          // compute map: 16x16 threads

    float acc[8][8];
#pragma unroll
    for (int i = 0; i < 8; i++)
#pragma unroll
        for (int j = 0; j < 8; j++) acc[i][j] = 0.f;

    for (int k0 = 0; k0 < HID; k0 += BK) {
        float4 a = *(const float4*)&d_X[(size_t)(m0 + lm) * HID + k0 + lk];
        float4 b = *(const float4*)&Wih[(size_t)(n0 + lm) * HID + k0 + lk];
        As[lk + 0][lm] = a.x; As[lk + 1][lm] = a.y; As[lk + 2][lm] = a.z; As[lk + 3][lm] = a.w;
        Bs[lk + 0][lm] = b.x; Bs[lk + 1][lm] = b.y; Bs[lk + 2][lm] = b.z; Bs[lk + 3][lm] = b.w;
        __syncthreads();
#pragma unroll
        for (int k = 0; k < BK; k++) {
            float ar[8], br[8];
#pragma unroll
            for (int i = 0; i < 8; i++) ar[i] = As[k][ty * 8 + i];
#pragma unroll
            for (int j = 0; j < 8; j++) br[j] = Bs[k][tx * 8 + j];
#pragma unroll
            for (int i = 0; i < 8; i++)
#pragma unroll
                for (int j = 0; j < 8; j++) acc[i][j] += ar[i] * br[j];
        }
        __syncthreads();
    }
#pragma unroll
    for (int i = 0; i < 8; i++) {
        size_t rbase = (size_t)(m0 + ty * 8 + i) * G3;
#pragma unroll
        for (int j = 0; j < 8; j++) {
            int n = n0 + tx * 8 + j;
            d_GI[rbase + n] = acc[i][j] + bih[n];
        }
    }
}

// -------------------- 4) levels via pointer jumping + counting sort ---------
__global__ void k_levels(const int* __restrict__ tree) {
    __shared__ int anc[NNODE];
    __shared__ int dep[NNODE];
    __shared__ int s_max;
    int t = threadIdx.x, NT = blockDim.x;     // 512

    for (int c = t; c < NNODE; c += NT) {
        if (c == 0) { anc[0] = 0; dep[0] = 0; }
        else        { anc[c] = tree[2 * (c - 1)]; dep[c] = 1; }
    }
    if (t == 0) s_max = 0;
    __syncthreads();

    for (int it = 0; it < 13; it++) {         // 2^13 > max possible depth
        int na[9], nd[9];
        int i = 0;
        for (int c = t; c < NNODE; c += NT, i++) {
            int a = anc[c];
            nd[i] = dep[c] + dep[a];
            na[i] = anc[a];
        }
        __syncthreads();
        i = 0;
        for (int c = t; c < NNODE; c += NT, i++) { dep[c] = nd[i]; anc[c] = na[i]; }
        __syncthreads();
    }

    int lm = 0;
    for (int c = t; c < NNODE; c += NT) lm = max(lm, dep[c]);
    atomicMax(&s_max, lm);
    // reuse anc as histogram / running offsets
    for (int c = t; c < NNODE; c += NT) anc[c] = 0;
    __syncthreads();
    for (int c = t; c < NNODE; c += NT)
        if (c > 0) atomicAdd(&anc[dep[c]], 1);
    __syncthreads();
    if (t == 0) {
        int ml = s_max;                        // true depth (<= NLEV_MAX assumed)
        int run = 0;
        for (int l = 1; l <= NLEV_MAX; l++) {
            if (l <= ml) {
                d_levelStart[l] = run;
                int h = anc[l];
                anc[l] = run;
                run += h;
            } else {
                d_levelStart[l] = run;         // empty levels beyond depth
            }
        }
        d_levelStart[NLEV_MAX + 1] = run;      // == NEDGE when ml <= NLEV_MAX
        d_levelStart[0] = 0;
    }
    __syncthreads();
    for (int c = t; c < NNODE; c += NT)
        if (c > 0) {
            int pos = atomicAdd(&anc[dep[c]], 1);
            d_order[pos] = c;
        }
    for (int u = t; u < HID; u += NT) d_H[u] = 0.f;  // root hidden state
}

// -------------------- 5a) per-level GH = W_hh @ h_parent + b_hh -------------
// 192 blocks x 256 thr = 1536 warps, one W_hh row per warp (weight-stationary
// within the level). Each warp loops over this level's nodes 4 at a time.
__global__ __launch_bounds__(256) void k_gh(int lev, const int* __restrict__ tree,
                                            const float* __restrict__ Whh,
                                            const float* __restrict__ bhh) {
    int s = d_levelStart[lev], e = d_levelStart[lev + 1];
    if (s >= e) return;
    int lane = threadIdx.x & 31;
    int row = (blockIdx.x * blockDim.x + threadIdx.x) >> 5;   // 0..1535

    float wreg[16];
#pragma unroll
    for (int i = 0; i < 16; i++) wreg[i] = Whh[(size_t)row * HID + i * 32 + lane];
    float brow = bhh[row];

    for (int j = s; j < e; j += 4) {
        int n = e - j; if (n > 4) n = 4;
        int cq[4];
        const float* hp[4];
#pragma unroll
        for (int q = 0; q < 4; q++) {
            int jj = j + (q < n ? q : 0);
            int c = d_order[jj];
            cq[q] = c;
            hp[q] = &d_H[(size_t)tree[2 * (c - 1)] * HID];
        }
        float a0 = 0.f, a1 = 0.f, a2 = 0.f, a3 = 0.f;
#pragma unroll
        for (int i = 0; i < 16; i++) {
            int u = i * 32 + lane;
            float w = wreg[i];
            a0 += w * hp[0][u];
            a1 += w * hp[1][u];
            a2 += w * hp[2][u];
            a3 += w * hp[3][u];
        }
#pragma unroll
        for (int o = 16; o > 0; o >>= 1) {
            a0 += __shfl_down_sync(0xffffffffu, a0, o);
            a1 += __shfl_down_sync(0xffffffffu, a1, o);
            a2 += __shfl_down_sync(0xffffffffu, a2, o);
            a3 += __shfl_down_sync(0xffffffffu, a3, o);
        }
        if (lane == 0) {
            float av[4] = {a0, a1, a2, a3};
#pragma unroll
            for (int q = 0; q < 4; q++)
                if (q < n) d_GH[(size_t)(cq[q] - 1) * G3 + row] = av[q] + brow;
        }
    }
}

// -------------------- 5b) per-level GRU combine -----------------------------
__global__ __launch_bounds__(256) void k_combine(int lev, const int* __restrict__ tree) {
    int s = d_levelStart[lev], e = d_levelStart[lev + 1];
    int total = (e - s) * HID;
    for (int idx = blockIdx.x * blockDim.x + threadIdx.x; idx < total;
         idx += gridDim.x * blockDim.x) {
        int j = s + (idx >> 9);
        int u = idx & 511;
        int c = d_order[j];
        size_t gb = (size_t)(c - 1) * G3;
        float gr = d_GI[gb + u], gz = d_GI[gb + HID + u], gn = d_GI[gb + 2 * HID + u];
        float hr = d_GH[gb + u], hz = d_GH[gb + HID + u], hn = d_GH[gb + 2 * HID + u];
        float r = 1.f / (1.f + __expf(-(gr + hr)));
        float z = 1.f / (1.f + __expf(-(gz + hz)));
        float n = tanhf(gn + r * hn);
        int p = tree[2 * (c - 1)];
        float hpu = d_H[(size_t)p * HID + u];
        d_H[(size_t)c * HID + u] = (1.f - z) * n + z * hpu;
    }
}

// -------------------- 6) leaf max -> logits -> softmax ----------------------
__global__ void k_final(const int* __restrict__ tree, const float* __restrict__ outW,
                        const float* __restrict__ outb, float* __restrict__ out) {
    __shared__ unsigned char leaf[NNODE];
    __shared__ float fin[HID];
    __shared__ float logits[NCLS];
    int t = threadIdx.x;
    for (int c = t; c < NNODE; c += blockDim.x) leaf[c] = 1;
    __syncthreads();
    for (int e = t; e < NEDGE; e += blockDim.x) leaf[tree[2 * e]] = 0;
    __syncthreads();
    float m = -1e30f;
    for (int c = 0; c < NNODE; c++)
        if (leaf[c]) m = fmaxf(m, d_H[(size_t)c * HID + t]);
    fin[t] = m;
    __syncthreads();
    if (t < NCLS * 32) {
        int cls = t >> 5, lane = t & 31;
        float s = 0.f;
        for (int u = lane; u < HID; u += 32) s += outW[cls * HID + u] * fin[u];
#pragma unroll
        for (int o = 16; o > 0; o >>= 1) s += __shfl_down_sync(0xffffffffu, s, o);
        if (lane == 0) logits[cls] = s + outb[cls];
    }
    __syncthreads();
    if (t == 0) {
        float mx = logits[0];
        for (int i = 1; i < NCLS; i++) mx = fmaxf(mx, logits[i]);
        float ex[NCLS], sm = 0.f;
        for (int i = 0; i < NCLS; i++) { ex[i] = expf(logits[i] - mx); sm += ex[i]; }
        for (int i = 0; i < NCLS; i++) out[i] = ex[i] / sm;
    }
}

// -------------------- launcher ----------------------------------------------
extern "C" void kernel_launch(void* const* d_in, const int* in_sizes, int n_in,
                              void* d_out, int out_size) {
    const int*   tree = (const int*)  d_in[0];
    const float* word = (const float*)d_in[1];
    const int*   widx = (const int*)  d_in[2];
    const float* Etab = (const float*)d_in[3];
    const float* Wih  = (const float*)d_in[4];
    const float* Whh  = (const float*)d_in[5];
    const float* bih  = (const float*)d_in[6];
    const float* bhh  = (const float*)d_in[7];
    const float* outW = (const float*)d_in[8];
    const float* outb = (const float*)d_in[9];
    float* out = (float*)d_out;

    k_transpose<<<dim3((VOCAB + 31) / 32, HID / 32), dim3(32, 8)>>>(Etab);
    k_embed<<<NEDGE, 128>>>(word, widx);
    k_gi<<<dim3(G3 / BN, NEDGE / BM), 256>>>(Wih, bih);
    k_levels<<<1, 512>>>(tree);
    for (int lev = 1; lev <= NLEV_MAX; lev++) {
        k_gh<<<192, 256>>>(lev, tree, Whh, bhh);
        k_combine<<<128, 256>>>(lev, tree);
    }
    k_final<<<1, 512>>>(tree, outW, outb, out);
}

// round 5
// speedup vs baseline: 3.6740x; 3.6740x over previous
#include <cuda_runtime.h>
#include <math.h>

#define VOCAB 30000
#define HID   512
#define NCLS  4
#define NEDGE 4096
#define NNODE (NEDGE + 1)
#define KW    32
#define G3    (3 * HID)      // 1536
#define NLEV_MAX 40          // depth of random recursive tree n=4097 ~ e*ln(n) ~ 22

// -------------------- static device scratch (no allocations allowed) --------
__device__ float d_Et[(size_t)VOCAB * HID];
__device__ float d_X [(size_t)NEDGE * HID];
__device__ float d_GI[(size_t)NEDGE * G3];
__device__ float d_GH[(size_t)NEDGE * G3];
__device__ float d_H [(size_t)NNODE * HID];
__device__ int   d_order[NEDGE];
__device__ int   d_levelStart[NLEV_MAX + 2];
__device__ unsigned char d_leaf[NNODE];
__device__ unsigned d_finU[HID];

// -------------------- 1) transpose E (HID,VOCAB) -> (VOCAB,HID) -------------
__global__ void k_transpose(const float* __restrict__ E) {
    __shared__ float t[32][33];
    int v0 = blockIdx.x * 32, h0 = blockIdx.y * 32;
    int vx = v0 + threadIdx.x;
#pragma unroll
    for (int i = 0; i < 32; i += 8) {
        int h = h0 + threadIdx.y + i;
        if (vx < VOCAB) t[threadIdx.y + i][threadIdx.x] = E[(size_t)h * VOCAB + vx];
    }
    __syncthreads();
    int hx = h0 + threadIdx.x;
#pragma unroll
    for (int i = 0; i < 32; i += 8) {
        int v = v0 + threadIdx.y + i;
        if (v < VOCAB) d_Et[(size_t)v * HID + hx] = t[threadIdx.x][threadIdx.y + i];
    }
}

// -------------------- 2) x[c] = sum_k Et[idx[c][k]] * w[c][k] ---------------
__global__ void k_embed(const float* __restrict__ word, const int* __restrict__ widx) {
    int c = blockIdx.x;
    __shared__ int   si[KW];
    __shared__ float sw[KW];
    if (threadIdx.x < KW) {
        si[threadIdx.x] = widx[c * KW + threadIdx.x];
        sw[threadIdx.x] = word[c * KW + threadIdx.x];
    }
    __syncthreads();
    int h = threadIdx.x;
    float a0 = 0.f, a1 = 0.f, a2 = 0.f, a3 = 0.f;
#pragma unroll 4
    for (int k = 0; k < KW; k++) {
        const float* ep = &d_Et[(size_t)si[k] * HID];
        float wk = sw[k];
        a0 += ep[h]       * wk;
        a1 += ep[h + 128] * wk;
        a2 += ep[h + 256] * wk;
        a3 += ep[h + 384] * wk;
    }
    float* xp = &d_X[(size_t)c * HID];
    xp[h] = a0; xp[h + 128] = a1; xp[h + 256] = a2; xp[h + 384] = a3;
}

// -------------------- 3) GI = X @ W_ih^T + b_ih  (4096 x 1536, K=512) -------
#define BM 128
#define BN 128
#define BK 8
__global__ __launch_bounds__(256) void k_gi(const float* __restrict__ Wih,
                                            const float* __restrict__ bih) {
    __shared__ float As[BK][BM];
    __shared__ float Bs[BK][BN];
    int m0 = blockIdx.y * BM, n0 = blockIdx.x * BN;
    int tid = threadIdx.x;
    int lm = tid >> 1, lk = (tid & 1) * 4;
    int ty = tid >> 4, tx = tid & 15;

    float acc[8][8];
#pragma unroll
    for (int i = 0; i < 8; i++)
#pragma unroll
        for (int j = 0; j < 8; j++) acc[i][j] = 0.f;

    for (int k0 = 0; k0 < HID; k0 += BK) {
        float4 a = *(const float4*)&d_X[(size_t)(m0 + lm) * HID + k0 + lk];
        float4 b = *(const float4*)&Wih[(size_t)(n0 + lm) * HID + k0 + lk];
        As[lk + 0][lm] = a.x; As[lk + 1][lm] = a.y; As[lk + 2][lm] = a.z; As[lk + 3][lm] = a.w;
        Bs[lk + 0][lm] = b.x; Bs[lk + 1][lm] = b.y; Bs[lk + 2][lm] = b.z; Bs[lk + 3][lm] = b.w;
        __syncthreads();
#pragma unroll
        for (int k = 0; k < BK; k++) {
            float4 ar0 = *(const float4*)&As[k][ty * 8];
            float4 ar1 = *(const float4*)&As[k][ty * 8 + 4];
            float4 br0 = *(const float4*)&Bs[k][tx * 8];
            float4 br1 = *(const float4*)&Bs[k][tx * 8 + 4];
            float ar[8] = {ar0.x, ar0.y, ar0.z, ar0.w, ar1.x, ar1.y, ar1.z, ar1.w};
            float br[8] = {br0.x, br0.y, br0.z, br0.w, br1.x, br1.y, br1.z, br1.w};
#pragma unroll
            for (int i = 0; i < 8; i++)
#pragma unroll
                for (int j = 0; j < 8; j++) acc[i][j] += ar[i] * br[j];
        }
        __syncthreads();
    }
#pragma unroll
    for (int i = 0; i < 8; i++) {
        size_t rbase = (size_t)(m0 + ty * 8 + i) * G3;
#pragma unroll
        for (int j = 0; j < 8; j++) {
            int n = n0 + tx * 8 + j;
            d_GI[rbase + n] = acc[i][j] + bih[n];
        }
    }
}

// -------------------- 4) levels via pointer jumping + counting sort ---------
__global__ void k_levels(const int* __restrict__ tree) {
    __shared__ int anc[NNODE];
    __shared__ int dep[NNODE];
    __shared__ int s_max;
    int t = threadIdx.x, NT = blockDim.x;     // 512

    for (int c = t; c < NNODE; c += NT) {
        if (c == 0) { anc[0] = 0; dep[0] = 0; }
        else        { anc[c] = tree[2 * (c - 1)]; dep[c] = 1; }
        d_leaf[c] = 1;
    }
    if (t == 0) s_max = 0;
    for (int u = t; u < HID; u += NT) { d_finU[u] = 0u; d_H[u] = 0.f; }
    __syncthreads();

    for (int it = 0; it < 13; it++) {
        int na[9], nd[9];
        int i = 0;
        for (int c = t; c < NNODE; c += NT, i++) {
            int a = anc[c];
            nd[i] = dep[c] + dep[a];
            na[i] = anc[a];
        }
        __syncthreads();
        i = 0;
        for (int c = t; c < NNODE; c += NT, i++) { dep[c] = nd[i]; anc[c] = na[i]; }
        __syncthreads();
    }

    int lm = 0;
    for (int c = t; c < NNODE; c += NT) lm = max(lm, dep[c]);
    atomicMax(&s_max, lm);
    for (int e = t; e < NEDGE; e += NT) d_leaf[tree[2 * e]] = 0;
    for (int c = t; c < NNODE; c += NT) anc[c] = 0;  // reuse as histogram
    __syncthreads();
    for (int c = t; c < NNODE; c += NT)
        if (c > 0) atomicAdd(&anc[dep[c]], 1);
    __syncthreads();
    if (t == 0) {
        int ml = s_max;                        // assumed <= NLEV_MAX
        int run = 0;
        for (int l = 1; l <= NLEV_MAX; l++) {
            d_levelStart[l] = run;
            if (l <= ml) {
                int h = anc[l];
                anc[l] = run;
                run += h;
            }
        }
        d_levelStart[0] = 0;
        d_levelStart[NLEV_MAX + 1] = run;      // == NEDGE
    }
    __syncthreads();
    for (int c = t; c < NNODE; c += NT)
        if (c > 0) {
            int pos = atomicAdd(&anc[dep[c]], 1);
            d_order[pos] = c;
        }
}

// -------------------- 5a) per-level GH GEMM ---------------------------------
// GH[c][r] = sum_k Whh[r][k] * H[parent(c)][k]  for nodes c in level.
// Tiles: 64 rows x 32 nodes, K chunked by 16. Grid-stride over tiles.
#define GM 64
#define GN 32
#define GK 16
#define GH_ROWBLKS (G3 / GM)   // 24
__global__ __launch_bounds__(256) void k_gh(int lev, const int* __restrict__ tree,
                                            const float* __restrict__ Whh,
                                            const float* __restrict__ bhh) {
    int s = d_levelStart[lev], e = d_levelStart[lev + 1];
    int cnt = e - s;
    if (cnt <= 0) return;
    int nodeBlocks = (cnt + GN - 1) / GN;
    int tiles = nodeBlocks * GH_ROWBLKS;

    __shared__ float As[GK][GM];       // [k][row]
    __shared__ float Bs[GK][GN + 2];   // [k][node]
    __shared__ int   sp[GN];           // parent node ids
    __shared__ int   sc[GN];           // child-1 (edge) ids
    int tid = threadIdx.x;
    int ty = tid >> 4;                 // 0..15 -> rows ty*4 .. ty*4+3
    int tx = tid & 15;                 // 0..15 -> nodes tx*2, tx*2+1

    for (int t = blockIdx.x; t < tiles; t += gridDim.x) {
        int rb = t % GH_ROWBLKS, nb = t / GH_ROWBLKS;
        int r0 = rb * GM, j0 = nb * GN;
        if (tid < GN) {
            int jj = j0 + tid;
            int cl = d_order[s + (jj < cnt ? jj : cnt - 1)];
            sp[tid] = tree[2 * (cl - 1)];
            sc[tid] = cl - 1;
        }
        __syncthreads();

        float acc[4][2];
#pragma unroll
        for (int i = 0; i < 4; i++) { acc[i][0] = 0.f; acc[i][1] = 0.f; }

        for (int k0 = 0; k0 < HID; k0 += GK) {
            {   // As: 64 rows x 16 k = 256 float4s, one per thread
                int row = tid >> 2, kk = (tid & 3) * 4;
                float4 v = *(const float4*)&Whh[(size_t)(r0 + row) * HID + k0 + kk];
                As[kk + 0][row] = v.x; As[kk + 1][row] = v.y;
                As[kk + 2][row] = v.z; As[kk + 3][row] = v.w;
            }
            if (tid < 128) {  // Bs: 32 nodes x 16 k = 128 float4s
                int j = tid >> 2, kk = (tid & 3) * 4;
                float4 v = *(const float4*)&d_H[(size_t)sp[j] * HID + k0 + kk];
                Bs[kk + 0][j] = v.x; Bs[kk + 1][j] = v.y;
                Bs[kk + 2][j] = v.z; Bs[kk + 3][j] = v.w;
            }
            __syncthreads();
#pragma unroll
            for (int k = 0; k < GK; k++) {
                float4 a = *(const float4*)&As[k][ty * 4];
                float b0 = Bs[k][tx * 2], b1 = Bs[k][tx * 2 + 1];
                acc[0][0] += a.x * b0; acc[0][1] += a.x * b1;
                acc[1][0] += a.y * b0; acc[1][1] += a.y * b1;
                acc[2][0] += a.z * b0; acc[2][1] += a.z * b1;
                acc[3][0] += a.w * b0; acc[3][1] += a.w * b1;
            }
            __syncthreads();
        }
#pragma unroll
        for (int q = 0; q < 2; q++) {
            int j = j0 + tx * 2 + q;
            if (j < cnt) {
                size_t base = (size_t)sc[tx * 2 + q] * G3;
#pragma unroll
                for (int i = 0; i < 4; i++) {
                    int r = r0 + ty * 4 + i;
                    d_GH[base + r] = acc[i][q] + bhh[r];
                }
            }
        }
        __syncthreads();
    }
}

// -------------------- 5b) per-level GRU combine -----------------------------
__global__ __launch_bounds__(256) void k_combine(int lev, const int* __restrict__ tree) {
    int s = d_levelStart[lev], e = d_levelStart[lev + 1];
    int total = (e - s) * HID;
    for (int idx = blockIdx.x * blockDim.x + threadIdx.x; idx < total;
         idx += gridDim.x * blockDim.x) {
        int j = s + (idx >> 9);
        int u = idx & 511;
        int c = d_order[j];
        size_t gb = (size_t)(c - 1) * G3;
        float gr = d_GI[gb + u], gz = d_GI[gb + HID + u], gn = d_GI[gb + 2 * HID + u];
        float hr = d_GH[gb + u], hz = d_GH[gb + HID + u], hn = d_GH[gb + 2 * HID + u];
        float r = 1.f / (1.f + __expf(-(gr + hr)));
        float z = 1.f / (1.f + __expf(-(gz + hz)));
        float n = tanhf(gn + r * hn);
        int p = tree[2 * (c - 1)];
        float hpu = d_H[(size_t)p * HID + u];
        d_H[(size_t)c * HID + u] = (1.f - z) * n + z * hpu;
    }
}

// -------------------- 6a) parallel leaf max (order-preserving uint) ---------
__global__ __launch_bounds__(512) void k_final1() {
    int u = threadIdx.x;
    int c0 = blockIdx.x * 64;
    float m = -2.f;                   // |h| <= 1 by GRU construction
#pragma unroll 4
    for (int i = 0; i < 64; i++) {
        int c = c0 + i;
        if (c < NNODE && d_leaf[c]) m = fmaxf(m, d_H[(size_t)c * HID + u]);
    }
    unsigned bits = __float_as_uint(m);
    unsigned enc = (bits & 0x80000000u) ? ~bits : (bits | 0x80000000u);
    atomicMax(&d_finU[u], enc);
}

// -------------------- 6b) logits + softmax ----------------------------------
__global__ void k_final2(const float* __restrict__ outW, const float* __restrict__ outb,
                         float* __restrict__ out) {
    __shared__ float fin[HID];
    __shared__ float logits[NCLS];
    int t = threadIdx.x;              // 128 threads
    for (int u = t; u < HID; u += 128) {
        unsigned enc = d_finU[u];
        unsigned bits = (enc & 0x80000000u) ? (enc & 0x7FFFFFFFu) : ~enc;
        fin[u] = __uint_as_float(bits);
    }
    __syncthreads();
    int cls = t >> 5, lane = t & 31;
    float s = 0.f;
    for (int u = lane; u < HID; u += 32) s += outW[cls * HID + u] * fin[u];
#pragma unroll
    for (int o = 16; o > 0; o >>= 1) s += __shfl_down_sync(0xffffffffu, s, o);
    if (lane == 0) logits[cls] = s + outb[cls];
    __syncthreads();
    if (t == 0) {
        float mx = logits[0];
        for (int i = 1; i < NCLS; i++) mx = fmaxf(mx, logits[i]);
        float ex[NCLS], sm = 0.f;
        for (int i = 0; i < NCLS; i++) { ex[i] = expf(logits[i] - mx); sm += ex[i]; }
        for (int i = 0; i < NCLS; i++) out[i] = ex[i] / sm;
    }
}

// -------------------- launcher ----------------------------------------------
extern "C" void kernel_launch(void* const* d_in, const int* in_sizes, int n_in,
                              void* d_out, int out_size) {
    const int*   tree = (const int*)  d_in[0];
    const float* word = (const float*)d_in[1];
    const int*   widx = (const int*)  d_in[2];
    const float* Etab = (const float*)d_in[3];
    const float* Wih  = (const float*)d_in[4];
    const float* Whh  = (const float*)d_in[5];
    const float* bih  = (const float*)d_in[6];
    const float* bhh  = (const float*)d_in[7];
    const float* outW = (const float*)d_in[8];
    const float* outb = (const float*)d_in[9];
    float* out = (float*)d_out;

    k_transpose<<<dim3((VOCAB + 31) / 32, HID / 32), dim3(32, 8)>>>(Etab);
    k_embed<<<NEDGE, 128>>>(word, widx);
    k_gi<<<dim3(G3 / BN, NEDGE / BM), 256>>>(Wih, bih);
    k_levels<<<1, 512>>>(tree);
    for (int lev = 1; lev <= NLEV_MAX; lev++) {
        k_gh<<<192, 256>>>(lev, tree, Whh, bhh);
        k_combine<<<128, 256>>>(lev, tree);
    }
    k_final1<<<(NNODE + 63) / 64, 512>>>();
    k_final2<<<1, 128>>>(outW, outb, out);
}